// round 4
// baseline (speedup 1.0000x reference)
#include <cuda_runtime.h>
#include <cuda_bf16.h>

#define NUM_LEVELS 32
#define SCALE_F 0.15f
#define BATCH 8
#define SEQ 8192
#define DIM 1024
#define NTOK (BATCH * SEQ)
#define NCHUNK (NTOK / 64)          // 1024 gather chunks of 64 tokens
#define BIGV 100000

// scratch (alloc-free rule: __device__ globals)
__device__ unsigned char g_levels[NTOK];
__device__ int4 g_comp[64];          // per (row, 1024-token chunk) composite (a,l,h,-)

// ---------------------------------------------------------------------------
// Composite algebra: f(x) = clip(x + a, l, h) is closed under composition.
// comp2(p,q) = "apply p first, then q".
// ---------------------------------------------------------------------------
struct Cmp { int a, l, h; };

__device__ __forceinline__ Cmp comp2(Cmp p, Cmp q) {
    Cmp r;
    r.a = p.a + q.a;
    r.l = min(max(p.l + q.a, q.l), q.h);
    r.h = min(max(p.h + q.a, q.l), q.h);
    return r;
}

__device__ __forceinline__ int delta_of(int t) {
    return (int)((t == 40) | (t == 91) | (t == 123))
         - (int)((t == 41) | (t == 93) | (t == 125));
}

__device__ __forceinline__ Cmp thread_comp(int4 t, int d[4]) {
    d[0] = delta_of(t.x); d[1] = delta_of(t.y);
    d[2] = delta_of(t.z); d[3] = delta_of(t.w);
    Cmp c = {0, -BIGV, BIGV};
#pragma unroll
    for (int i = 0; i < 4; i++) {
        c.a += d[i];
        c.l = min(max(c.l + d[i], 0), NUM_LEVELS - 1);
        c.h = min(max(c.h + d[i], 0), NUM_LEVELS - 1);
    }
    return c;
}

__device__ __forceinline__ Cmp warp_incl_scan(Cmp c, int lane) {
#pragma unroll
    for (int off = 1; off < 32; off <<= 1) {
        int pa = __shfl_up_sync(0xFFFFFFFFu, c.a, off);
        int pl = __shfl_up_sync(0xFFFFFFFFu, c.l, off);
        int ph = __shfl_up_sync(0xFFFFFFFFu, c.h, off);
        if (lane >= off) { Cmp p = {pa, pl, ph}; c = comp2(p, c); }
    }
    return c;
}

// ---------------------------------------------------------------------------
// Phase A: 64 blocks (8 rows x 8 chunks of 1024 tokens), 256 threads,
// 4 tokens/thread. Computes each chunk's (a,l,h) composite.
// ---------------------------------------------------------------------------
__global__ __launch_bounds__(256) void levels_phaseA(const int* __restrict__ tok) {
    const int b = blockIdx.x;
    const int tid = threadIdx.x;
    const int lane = tid & 31, warp = tid >> 5;

    int4 t = *(const int4*)(tok + b * 1024 + tid * 4);
    int d[4];
    Cmp c = thread_comp(t, d);
    c = warp_incl_scan(c, lane);

    __shared__ Cmp wc[8];
    if (lane == 31) wc[warp] = c;
    __syncthreads();

    if (tid == 0) {
        Cmp blk = wc[0];
#pragma unroll
        for (int w = 1; w < 8; w++) blk = comp2(blk, wc[w]);
        g_comp[b] = make_int4(blk.a, blk.l, blk.h, 0);
    }
}

// ---------------------------------------------------------------------------
// Phase B: same decomposition. Each block composes prior chunk composites in
// its row (<=7, serial, trivial) to get starting level x0, re-scans its chunk,
// and writes 4 levels/thread as a packed uint32.
// ---------------------------------------------------------------------------
__global__ __launch_bounds__(256) void levels_phaseB(const int* __restrict__ tok) {
    const int b = blockIdx.x;
    const int row = b >> 3, chunk = b & 7;
    const int tid = threadIdx.x;
    const int lane = tid & 31, warp = tid >> 5;

    // starting level for this chunk
    int x0 = 0;
    for (int i = row * 8; i < row * 8 + chunk; i++) {
        int4 f = g_comp[i];
        x0 = min(max(x0 + f.x, f.y), f.z);
    }

    int4 t = *(const int4*)(tok + b * 1024 + tid * 4);
    int d[4];
    Cmp c = thread_comp(t, d);
    Cmp incl = warp_incl_scan(c, lane);

    // exclusive within warp
    Cmp ex;
    ex.a = __shfl_up_sync(0xFFFFFFFFu, incl.a, 1);
    ex.l = __shfl_up_sync(0xFFFFFFFFu, incl.l, 1);
    ex.h = __shfl_up_sync(0xFFFFFFFFu, incl.h, 1);
    if (lane == 0) { ex.a = 0; ex.l = -BIGV; ex.h = BIGV; }

    __shared__ Cmp wc[8];
    if (lane == 31) wc[warp] = incl;
    __syncthreads();

    Cmp pre = {0, -BIGV, BIGV};
    for (int w = 0; w < warp; w++) pre = comp2(pre, wc[w]);
    pre = comp2(pre, ex);

    int x = min(max(x0 + pre.a, pre.l), pre.h);
    unsigned int packed = 0;
#pragma unroll
    for (int i = 0; i < 4; i++) {
        x = min(max(x + d[i], 0), NUM_LEVELS - 1);
        packed |= ((unsigned int)x) << (i * 8);
    }
    ((unsigned int*)g_levels)[b * 256 + tid] = packed;
}

// ---------------------------------------------------------------------------
// Gather: out[token, :] = scaled_emb[level[token], :]
// Pre-scaled table (32x1024 fp32 = 128 KB) in dynamic smem. 148 persistent
// blocks x 1024 threads. Grid-stride over 64-token chunks: each thread loads
// 16 level bytes (one uint4, hoisted off the critical path), then 16
// independent LDS.128 -> STG.128(streaming) pairs.
// ---------------------------------------------------------------------------
__global__ __launch_bounds__(1024) void gather_kernel(const float* __restrict__ emb,
                                                      float4* __restrict__ out) {
    extern __shared__ float semb[];
    const int tid = threadIdx.x;

    const float4* __restrict__ e4 = (const float4*)emb;
    float4* s4 = (float4*)semb;
    for (int i = tid; i < NUM_LEVELS * DIM / 4; i += 1024) {
        float4 v = e4[i];
        v.x *= SCALE_F; v.y *= SCALE_F; v.z *= SCALE_F; v.w *= SCALE_F;
        s4[i] = v;
    }
    __syncthreads();

    const int g = tid >> 8;    // which 16-token quarter of the chunk
    const int j = tid & 255;   // float4 index within the 1024-float row

    for (int c = blockIdx.x; c < NCHUNK; c += gridDim.x) {
        const uint4 lv = *(const uint4*)(g_levels + c * 64 + g * 16);
        const unsigned int w[4] = {lv.x, lv.y, lv.z, lv.w};
        float4* obase = out + (size_t)(c * 64 + g * 16) * (DIM / 4) + j;
#pragma unroll
        for (int k = 0; k < 16; k++) {
            const int lvl = (int)((w[k >> 2] >> ((k & 3) * 8)) & 0xFF);
            const float4 v = s4[lvl * (DIM / 4) + j];
            __stcs(obase + (size_t)k * (DIM / 4), v);
        }
    }
}

extern "C" void kernel_launch(void* const* d_in, const int* in_sizes, int n_in,
                              void* d_out, int out_size) {
    const int* token_ids = (const int*)d_in[0];
    const float* level_emb = (const float*)d_in[1];
    float4* out = (float4*)d_out;

    cudaFuncSetAttribute(gather_kernel,
                         cudaFuncAttributeMaxDynamicSharedMemorySize,
                         NUM_LEVELS * DIM * (int)sizeof(float));

    levels_phaseA<<<64, 256>>>(token_ids);
    levels_phaseB<<<64, 256>>>(token_ids);
    gather_kernel<<<148, 1024, NUM_LEVELS * DIM * sizeof(float)>>>(level_emb, out);
}

// round 5
// speedup vs baseline: 1.0372x; 1.0372x over previous
#include <cuda_runtime.h>
#include <cuda_bf16.h>

#define NUM_LEVELS 32
#define SCALE_F 0.15f
#define BATCH 8
#define SEQ 8192
#define DIM 1024
#define NTOK (BATCH * SEQ)
#define NCHUNK (NTOK / 64)          // 1024 gather chunks of 64 tokens
#define BIGV 100000

// scratch (alloc-free rule: __device__ globals)
__device__ unsigned char g_levels[NTOK];

// ---------------------------------------------------------------------------
// Composite algebra: f(x) = clip(x + a, l, h) is closed under composition.
// comp2(p,q) = "apply p first, then q".
// ---------------------------------------------------------------------------
struct Cmp { int a, l, h; };

__device__ __forceinline__ Cmp comp2(Cmp p, Cmp q) {
    Cmp r;
    r.a = p.a + q.a;
    r.l = min(max(p.l + q.a, q.l), q.h);
    r.h = min(max(p.h + q.a, q.l), q.h);
    return r;
}

__device__ __forceinline__ int delta_of(int t) {
    return (int)((t == 40) | (t == 91) | (t == 123))
         - (int)((t == 41) | (t == 93) | (t == 125));
}

__device__ __forceinline__ Cmp warp_incl_scan(Cmp c, int lane) {
#pragma unroll
    for (int off = 1; off < 32; off <<= 1) {
        int pa = __shfl_up_sync(0xFFFFFFFFu, c.a, off);
        int pl = __shfl_up_sync(0xFFFFFFFFu, c.l, off);
        int ph = __shfl_up_sync(0xFFFFFFFFu, c.h, off);
        if (lane >= off) { Cmp p = {pa, pl, ph}; c = comp2(p, c); }
    }
    return c;
}

// ---------------------------------------------------------------------------
// Levels: one kernel, 8 blocks (one per batch row) x 1024 threads,
// 8 tokens/thread. Shfl warp scan -> one smem stage (32 warp composites,
// scanned by warp 0) -> per-thread prefix. Only 2 __syncthreads.
// ---------------------------------------------------------------------------
__global__ __launch_bounds__(1024) void levels_kernel(const int* __restrict__ tok) {
    __shared__ Cmp wc[32];    // warp inclusive composites
    __shared__ Cmp we[32];    // warp exclusive prefixes
    const int b = blockIdx.x;
    const int tid = threadIdx.x;
    const int lane = tid & 31, warp = tid >> 5;

    const int base = b * SEQ + tid * 8;
    const int4 t0 = *(const int4*)(tok + base);
    const int4 t1 = *(const int4*)(tok + base + 4);

    int d[8];
    d[0] = delta_of(t0.x); d[1] = delta_of(t0.y);
    d[2] = delta_of(t0.z); d[3] = delta_of(t0.w);
    d[4] = delta_of(t1.x); d[5] = delta_of(t1.y);
    d[6] = delta_of(t1.z); d[7] = delta_of(t1.w);

    Cmp c = {0, -BIGV, BIGV};
#pragma unroll
    for (int i = 0; i < 8; i++) {
        c.a += d[i];
        c.l = min(max(c.l + d[i], 0), NUM_LEVELS - 1);
        c.h = min(max(c.h + d[i], 0), NUM_LEVELS - 1);
    }

    const Cmp incl = warp_incl_scan(c, lane);
    if (lane == 31) wc[warp] = incl;
    __syncthreads();

    if (warp == 0) {
        Cmp v = wc[lane];
        v = warp_incl_scan(v, lane);
        Cmp e;
        e.a = __shfl_up_sync(0xFFFFFFFFu, v.a, 1);
        e.l = __shfl_up_sync(0xFFFFFFFFu, v.l, 1);
        e.h = __shfl_up_sync(0xFFFFFFFFu, v.h, 1);
        if (lane == 0) { e.a = 0; e.l = -BIGV; e.h = BIGV; }
        we[lane] = e;
    }
    __syncthreads();

    // lane-exclusive composite within warp
    Cmp lex;
    lex.a = __shfl_up_sync(0xFFFFFFFFu, incl.a, 1);
    lex.l = __shfl_up_sync(0xFFFFFFFFu, incl.l, 1);
    lex.h = __shfl_up_sync(0xFFFFFFFFu, incl.h, 1);
    if (lane == 0) { lex.a = 0; lex.l = -BIGV; lex.h = BIGV; }

    const Cmp pre = comp2(we[warp], lex);   // warp prefix first, then lanes before us
    int x = min(max(pre.a, pre.l), pre.h);  // applied to initial level 0

    unsigned int p0 = 0, p1 = 0;
#pragma unroll
    for (int i = 0; i < 4; i++) {
        x = min(max(x + d[i], 0), NUM_LEVELS - 1);
        p0 |= ((unsigned int)x) << (i * 8);
    }
#pragma unroll
    for (int i = 4; i < 8; i++) {
        x = min(max(x + d[i], 0), NUM_LEVELS - 1);
        p1 |= ((unsigned int)x) << ((i - 4) * 8);
    }
    *(uint2*)(g_levels + base) = make_uint2(p0, p1);
}

// ---------------------------------------------------------------------------
// Gather: out[token, :] = scaled_emb[level[token], :]
// Pre-scaled table (32x1024 fp32 = 128 KB) in dynamic smem. 148 persistent
// blocks x 1024 threads. Grid-stride over 64-token chunks: each thread loads
// 16 level bytes (one uint4, hoisted), then 16 independent
// LDS.128 -> STG.128(streaming) pairs.
// ---------------------------------------------------------------------------
__global__ __launch_bounds__(1024) void gather_kernel(const float* __restrict__ emb,
                                                      float4* __restrict__ out) {
    extern __shared__ float semb[];
    const int tid = threadIdx.x;

    const float4* __restrict__ e4 = (const float4*)emb;
    float4* s4 = (float4*)semb;
    for (int i = tid; i < NUM_LEVELS * DIM / 4; i += 1024) {
        float4 v = e4[i];
        v.x *= SCALE_F; v.y *= SCALE_F; v.z *= SCALE_F; v.w *= SCALE_F;
        s4[i] = v;
    }
    __syncthreads();

    const int g = tid >> 8;    // which 16-token quarter of the chunk
    const int j = tid & 255;   // float4 index within the 1024-float row

    for (int c = blockIdx.x; c < NCHUNK; c += gridDim.x) {
        const uint4 lv = *(const uint4*)(g_levels + c * 64 + g * 16);
        const unsigned int w[4] = {lv.x, lv.y, lv.z, lv.w};
        float4* obase = out + (size_t)(c * 64 + g * 16) * (DIM / 4) + j;
#pragma unroll
        for (int k = 0; k < 16; k++) {
            const int lvl = (int)((w[k >> 2] >> ((k & 3) * 8)) & 0xFF);
            const float4 v = s4[lvl * (DIM / 4) + j];
            __stcs(obase + (size_t)k * (DIM / 4), v);
        }
    }
}

extern "C" void kernel_launch(void* const* d_in, const int* in_sizes, int n_in,
                              void* d_out, int out_size) {
    const int* token_ids = (const int*)d_in[0];
    const float* level_emb = (const float*)d_in[1];
    float4* out = (float4*)d_out;

    cudaFuncSetAttribute(gather_kernel,
                         cudaFuncAttributeMaxDynamicSharedMemorySize,
                         NUM_LEVELS * DIM * (int)sizeof(float));

    levels_kernel<<<BATCH, 1024>>>(token_ids);
    gather_kernel<<<148, 1024, NUM_LEVELS * DIM * sizeof(float)>>>(level_emb, out);
}